// round 4
// baseline (speedup 1.0000x reference)
#include <cuda_runtime.h>
#include <cstdint>
#include <cstddef>

// ---------------------------------------------------------------------------
// SwinSelfAttention fused kernel (fp32)
//   B=16, NW=256, S=64, D=256, H=8, HD=32
// One block per (b, nw) window. 256 threads.
// Per head: QKV projection GEMM -> logits GEMM -> bias/mask -> log_softmax ->
//           attn @ V -> write out.
// ---------------------------------------------------------------------------

namespace {
constexpr int Sc = 64;    // tokens per window
constexpr int Dc = 256;   // model dim
constexpr int Hc = 8;     // heads
constexpr int NWc = 256;  // windows per batch
constexpr int THREADS = 256;
constexpr float QSCALE = 0.17677669529663688f;  // 1/sqrt(32)

constexpr int XS_STRIDE = 257;  // X tile [64][257] (odd stride: 2-way max on scalar a-loads)
constexpr int WS_STRIDE = 98;   // W tile [64 k][98] (even: keeps float2 b-loads 8B aligned)
constexpr int QK_STRIDE = 68;   // Qt/Kt [32 d][68]
constexpr int LS_STRIDE = 68;   // Ls/At/Bs [64][68]

constexpr int OFF_XS = 0;
constexpr int OFF_WS = OFF_XS + 64 * XS_STRIDE;     // 16448
constexpr int OFF_QT = OFF_WS + 64 * WS_STRIDE;     // +6272
constexpr int OFF_KT = OFF_QT + 32 * QK_STRIDE;     // +2176
constexpr int OFF_VH = OFF_KT + 32 * QK_STRIDE;     // +2176
constexpr int OFF_LS = OFF_VH + 64 * 32;            // +2048
constexpr int OFF_AT = OFF_LS + 64 * LS_STRIDE;     // +4352
constexpr int OFF_BS = OFF_AT + 64 * LS_STRIDE;     // +4352
constexpr int SMEM_FLOATS = OFF_BS + 64 * LS_STRIDE;  // 42176 floats = 168704 B
}  // namespace

__global__ void __launch_bounds__(THREADS, 1)
swin_attn_kernel(const float* __restrict__ patches,
                 const float* __restrict__ wq, const float* __restrict__ bq,
                 const float* __restrict__ wk, const float* __restrict__ bk,
                 const float* __restrict__ wv, const float* __restrict__ bvp,
                 const float* __restrict__ pos_bias,
                 const unsigned char* __restrict__ mask,
                 float* __restrict__ out) {
    extern __shared__ float sm[];
    float* Xs = sm + OFF_XS;
    float* Ws = sm + OFF_WS;
    float* Qt = sm + OFF_QT;
    float* Kt = sm + OFF_KT;
    float* Vh = sm + OFF_VH;
    float* Ls = sm + OFF_LS;
    float* At = sm + OFF_AT;
    float* Bs = sm + OFF_BS;

    const int tid = threadIdx.x;
    const int bw  = blockIdx.x;             // b*NW + nw
    const int nw  = bw & (NWc - 1);
    const float* Xg = patches + (size_t)bw * (Sc * Dc);
    float* Og = out + (size_t)bw * (Sc * Dc);
    const float NEG_INF = __int_as_float(0xff800000);

    // ---- stage X tile (64x256) into Xs[m][k] (coalesced float4 reads) ----
    #pragma unroll
    for (int i = 0; i < 16; ++i) {
        int f4 = tid + i * THREADS;           // 0..4095 float4s
        int m = f4 >> 6, k4 = f4 & 63;
        float4 v = *reinterpret_cast<const float4*>(Xg + m * Dc + k4 * 4);
        float* d = Xs + m * XS_STRIDE + k4 * 4;
        d[0] = v.x; d[1] = v.y; d[2] = v.z; d[3] = v.w;
    }
    // ---- precompute relative-position bias table Bs[q][k] (head/window invariant) ----
    #pragma unroll
    for (int i = 0; i < 16; ++i) {
        int idx = tid + i * THREADS;          // 0..4095
        int q = idx >> 6, k = idx & 63;
        int ri = (q >> 3) - (k >> 3) + 7;     // [0,14]
        int rj = (q & 7)  - (k & 7)  + 7;     // [0,14]
        Bs[q * LS_STRIDE + k] = pos_bias[ri * 15 + rj];
    }
    // (first __syncthreads happens at top of the kt loop below)

    const int tm4 = (tid & 15) * 4;   // GEMM0 m base
    const int tn6 = (tid >> 4) * 6;   // GEMM0 n base

    for (int h = 0; h < Hc; ++h) {
        // ================= GEMM0: [Q|K|V]_h = X @ Wcat_h^T  (64 x 96) =========
        float acc[4][6];
        #pragma unroll
        for (int i = 0; i < 4; ++i)
            #pragma unroll
            for (int j = 0; j < 6; ++j) acc[i][j] = 0.f;

        for (int kt = 0; kt < 4; ++kt) {
            const int k0 = kt * 64;
            __syncthreads();  // previous consumers of Ws (and at h=0,kt=0: X/Bs stores) done
            // stage W k-tile: Ws[kk][row], row 0..31 -> Wq, 32..63 -> Wk, 64..95 -> Wv
            #pragma unroll
            for (int i = 0; i < 6; ++i) {
                int f4 = tid + i * THREADS;   // 0..1535
                int row = f4 >> 4;            // 0..95
                int k4  = f4 & 15;
                const float* src;
                if (row < 32)      src = wq + (h * 32 + row) * Dc;
                else if (row < 64) src = wk + (h * 32 + row - 32) * Dc;
                else               src = wv + (h * 32 + row - 64) * Dc;
                float4 v = *reinterpret_cast<const float4*>(src + k0 + k4 * 4);
                float* d = Ws + (k4 * 4) * WS_STRIDE + row;
                d[0] = v.x; d[WS_STRIDE] = v.y; d[2 * WS_STRIDE] = v.z; d[3 * WS_STRIDE] = v.w;
            }
            __syncthreads();

            const float* xp = Xs + tm4 * XS_STRIDE + k0;
            const float* wp = Ws + tn6;
            #pragma unroll 16
            for (int kk = 0; kk < 64; ++kk) {
                float a[4];
                a[0] = xp[kk];
                a[1] = xp[XS_STRIDE + kk];
                a[2] = xp[2 * XS_STRIDE + kk];
                a[3] = xp[3 * XS_STRIDE + kk];
                const float* w = wp + kk * WS_STRIDE;
                float2 b01 = *reinterpret_cast<const float2*>(w);
                float2 b23 = *reinterpret_cast<const float2*>(w + 2);
                float2 b45 = *reinterpret_cast<const float2*>(w + 4);
                float b[6] = {b01.x, b01.y, b23.x, b23.y, b45.x, b45.y};
                #pragma unroll
                for (int i = 0; i < 4; ++i)
                    #pragma unroll
                    for (int j = 0; j < 6; ++j)
                        acc[i][j] = fmaf(a[i], b[j], acc[i][j]);
            }
        }

        // ---- scatter results: Qt[d][m] (pre-scaled), Kt[d][m], Vh[m][d] + biases ----
        #pragma unroll
        for (int j = 0; j < 6; ++j) {
            int col = tn6 + j;
            if (col < 32) {
                float bb = bq[h * 32 + col];
                #pragma unroll
                for (int i = 0; i < 4; ++i)
                    Qt[col * QK_STRIDE + tm4 + i] = (acc[i][j] + bb) * QSCALE;
            } else if (col < 64) {
                int c = col - 32;
                float bb = bk[h * 32 + c];
                #pragma unroll
                for (int i = 0; i < 4; ++i)
                    Kt[c * QK_STRIDE + tm4 + i] = acc[i][j] + bb;
            } else {
                int c = col - 64;
                float bb = bvp[h * 32 + c];
                #pragma unroll
                for (int i = 0; i < 4; ++i)
                    Vh[(tm4 + i) * 32 + c] = acc[i][j] + bb;
            }
        }
        __syncthreads();

        // ================= GEMM1: logits = Qs @ K^T (+bias, mask) ==============
        {
            const int q0 = (tid & 15) * 4;
            const int k0 = (tid >> 4) * 4;
            float s4[4][4];
            #pragma unroll
            for (int i = 0; i < 4; ++i)
                #pragma unroll
                for (int j = 0; j < 4; ++j) s4[i][j] = 0.f;

            const float* qp = Qt + q0;
            const float* kp = Kt + k0;
            #pragma unroll 8
            for (int d = 0; d < 32; ++d) {
                float4 a = *reinterpret_cast<const float4*>(qp + d * QK_STRIDE);
                float4 b = *reinterpret_cast<const float4*>(kp + d * QK_STRIDE);
                float av[4] = {a.x, a.y, a.z, a.w};
                float bvv[4] = {b.x, b.y, b.z, b.w};
                #pragma unroll
                for (int i = 0; i < 4; ++i)
                    #pragma unroll
                    for (int j = 0; j < 4; ++j)
                        s4[i][j] = fmaf(av[i], bvv[j], s4[i][j]);
            }
            const unsigned char* mp = mask + ((size_t)(nw * Hc + h) << 12);
            #pragma unroll
            for (int i = 0; i < 4; ++i) {
                int q = q0 + i;
                float4 bias4 = *reinterpret_cast<const float4*>(Bs + q * LS_STRIDE + k0);
                unsigned int mw = *reinterpret_cast<const unsigned int*>(mp + q * 64 + k0);
                float v0 = s4[i][0] + bias4.x;
                float v1 = s4[i][1] + bias4.y;
                float v2 = s4[i][2] + bias4.z;
                float v3 = s4[i][3] + bias4.w;
                if (mw) {  // rare: dataset mask is all-false
                    if (mw & 0x000000ffu) v0 = NEG_INF;
                    if (mw & 0x0000ff00u) v1 = NEG_INF;
                    if (mw & 0x00ff0000u) v2 = NEG_INF;
                    if (mw & 0xff000000u) v3 = NEG_INF;
                }
                *reinterpret_cast<float4*>(Ls + q * LS_STRIDE + k0) =
                    make_float4(v0, v1, v2, v3);
            }
        }
        __syncthreads();

        // ================= log_softmax over k, store transposed At[k][q] =======
        {
            const int q = tid >> 2;     // row
            const int r = tid & 3;      // quarter of the row
            const float* lp = Ls + q * LS_STRIDE + r * 16;
            float x[16];
            #pragma unroll
            for (int i = 0; i < 4; ++i) {
                float4 v = *reinterpret_cast<const float4*>(lp + i * 4);
                x[4 * i + 0] = v.x; x[4 * i + 1] = v.y;
                x[4 * i + 2] = v.z; x[4 * i + 3] = v.w;
            }
            float mx = x[0];
            #pragma unroll
            for (int i = 1; i < 16; ++i) mx = fmaxf(mx, x[i]);
            mx = fmaxf(mx, __shfl_xor_sync(0xffffffffu, mx, 1));
            mx = fmaxf(mx, __shfl_xor_sync(0xffffffffu, mx, 2));
            float ssum = 0.f;
            #pragma unroll
            for (int i = 0; i < 16; ++i) ssum += __expf(x[i] - mx);
            ssum += __shfl_xor_sync(0xffffffffu, ssum, 1);
            ssum += __shfl_xor_sync(0xffffffffu, ssum, 2);
            float lse = mx + __logf(ssum);
            #pragma unroll
            for (int i = 0; i < 16; ++i)
                At[(r * 16 + i) * LS_STRIDE + q] = x[i] - lse;
        }
        __syncthreads();

        // ================= GEMM2: out_h = attn @ V  (64 x 32) ==================
        {
            const int q0 = (tid & 15) * 4;
            const int d0 = (tid >> 4) * 2;
            float o[4][2];
            #pragma unroll
            for (int i = 0; i < 4; ++i) { o[i][0] = 0.f; o[i][1] = 0.f; }
            #pragma unroll 8
            for (int k = 0; k < 64; ++k) {
                float4 a = *reinterpret_cast<const float4*>(At + k * LS_STRIDE + q0);
                float2 b = *reinterpret_cast<const float2*>(Vh + k * 32 + d0);
                float av[4] = {a.x, a.y, a.z, a.w};
                #pragma unroll
                for (int i = 0; i < 4; ++i) {
                    o[i][0] = fmaf(av[i], b.x, o[i][0]);
                    o[i][1] = fmaf(av[i], b.y, o[i][1]);
                }
            }
            #pragma unroll
            for (int i = 0; i < 4; ++i) {
                *reinterpret_cast<float2*>(Og + (q0 + i) * Dc + h * 32 + d0) =
                    make_float2(o[i][0], o[i][1]);
            }
        }
        // next head's kt-loop top __syncthreads separates GEMM2 reads from
        // the next head's Qt/Kt/Vh overwrites.
    }
}

extern "C" void kernel_launch(void* const* d_in, const int* in_sizes, int n_in,
                              void* d_out, int out_size) {
    (void)in_sizes; (void)n_in; (void)out_size;
    const float* patches = (const float*)d_in[0];
    const float* wq = (const float*)d_in[1];
    const float* bq = (const float*)d_in[2];
    const float* wk = (const float*)d_in[3];
    const float* bk = (const float*)d_in[4];
    const float* wv = (const float*)d_in[5];
    const float* bv = (const float*)d_in[6];
    const float* pos = (const float*)d_in[7];
    const unsigned char* mask = (const unsigned char*)d_in[8];
    float* out = (float*)d_out;

    const size_t smem_bytes = (size_t)SMEM_FLOATS * sizeof(float);  // 168704 B
    cudaFuncSetAttribute(swin_attn_kernel,
                         cudaFuncAttributeMaxDynamicSharedMemorySize,
                         (int)smem_bytes);
    swin_attn_kernel<<<16 * 256, THREADS, smem_bytes>>>(
        patches, wq, bq, wk, bk, wv, bv, pos, mask, out);
}

// round 5
// speedup vs baseline: 1.0380x; 1.0380x over previous
#include <cuda_runtime.h>
#include <cstdint>
#include <cstddef>

// ---------------------------------------------------------------------------
// SwinSelfAttention fused kernel v2 (fp32, packed f32x2 FFMA)
//   B=16, NW=256, S=64, D=256, H=8, HD=32
// One block per window, 256 threads. Heads processed 2 at a time:
//   GEMM0 (X @ Wcat^T, 64x192) with 8m x 6n per-thread tiles + FFMA2,
//   then per-head: logits GEMM -> bias/mask -> log_softmax -> attn @ V.
// X is held k-major in SMEM (one-time two-step transpose) so GEMM0 a-loads
// are single-wavefront LDS.128.
// ---------------------------------------------------------------------------

namespace {
constexpr int Sc = 64;
constexpr int Dc = 256;
constexpr int Hc = 8;
constexpr int NWc = 256;
constexpr int THREADS = 256;
constexpr float QSCALE = 0.17677669529663688f;  // 1/sqrt(32)

constexpr int XT_STRIDE = 68;   // Xt[k=256][68]: cols 0..31 = m 0..31, cols 36..67 = m 32..63
constexpr int XN_STRIDE = 257;  // staging Xnat[m=64][257]
constexpr int WS_STRIDE = 194;  // Ws[k=64][194] (192 rows used)
constexpr int QK_STRIDE = 68;   // Qt/Kt per head [32][68]
constexpr int LS_STRIDE = 68;   // Ls/At/Bs [64][68]

constexpr int OFF_XT = 0;                          // 17408 floats
constexpr int OFF_U  = OFF_XT + 256 * XT_STRIDE;   // union base (Xnat aliases here)
constexpr int OFF_WS = OFF_U;                      // 12416
constexpr int OFF_QT = OFF_WS + 64 * WS_STRIDE;    // 2*32*68 = 4352
constexpr int OFF_KT = OFF_QT + 2 * 32 * QK_STRIDE;
constexpr int OFF_VH = OFF_KT + 2 * 32 * QK_STRIDE; // 2*64*32 = 4096
constexpr int OFF_LS = OFF_VH + 2 * 64 * 32;
constexpr int OFF_AT = OFF_LS + 64 * LS_STRIDE;
constexpr int OFF_BS = OFF_AT + 64 * LS_STRIDE;    // beyond Xnat (16448) -> no alias
constexpr int SMEM_FLOATS = OFF_BS + 64 * LS_STRIDE;  // 55680 floats = 222720 B
static_assert(OFF_BS - OFF_U >= 64 * XN_STRIDE, "Bs must not alias Xnat");

using ull = unsigned long long;
}  // namespace

__device__ __forceinline__ void ffma2(ull& d, ull a, ull b) {
    asm("fma.rn.f32x2 %0, %1, %2, %0;" : "+l"(d) : "l"(a), "l"(b));
}
__device__ __forceinline__ ull pack2(float x) {
    ull r; unsigned u = __float_as_uint(x);
    asm("mov.b64 %0, {%1, %1};" : "=l"(r) : "r"(u));
    return r;
}
__device__ __forceinline__ float2 unpack2(ull v) {
    unsigned lo, hi;
    asm("mov.b64 {%0, %1}, %2;" : "=r"(lo), "=r"(hi) : "l"(v));
    return make_float2(__uint_as_float(lo), __uint_as_float(hi));
}

__global__ void __launch_bounds__(THREADS, 1)
swin_attn_kernel(const float* __restrict__ patches,
                 const float* __restrict__ wq, const float* __restrict__ bq,
                 const float* __restrict__ wk, const float* __restrict__ bk,
                 const float* __restrict__ wv, const float* __restrict__ bvp,
                 const float* __restrict__ pos_bias,
                 const unsigned char* __restrict__ mask,
                 float* __restrict__ out) {
    extern __shared__ float sm[];
    float* Xt   = sm + OFF_XT;
    float* Xnat = sm + OFF_U;     // transient, aliases Ws/Qt/Kt
    float* Ws   = sm + OFF_WS;
    float* Qt2  = sm + OFF_QT;
    float* Kt2  = sm + OFF_KT;
    float* Vh2  = sm + OFF_VH;
    float* Ls   = sm + OFF_LS;
    float* At   = sm + OFF_AT;
    float* Bs   = sm + OFF_BS;

    const int tid = threadIdx.x;
    const int bw  = blockIdx.x;
    const int nw  = bw & (NWc - 1);
    const float* Xg = patches + (size_t)bw * (Sc * Dc);
    float* Og = out + (size_t)bw * (Sc * Dc);
    const float NEG_INF = __int_as_float(0xff800000);

    // ---- stage X (64x256) into Xnat[m][k], coalesced float4 global reads ----
    #pragma unroll
    for (int i = 0; i < 16; ++i) {
        int f4 = tid + i * THREADS;          // 0..4095
        int m = f4 >> 6, k4 = f4 & 63;
        float4 v = *reinterpret_cast<const float4*>(Xg + m * Dc + k4 * 4);
        float* d = Xnat + m * XN_STRIDE + k4 * 4;
        d[0] = v.x; d[1] = v.y; d[2] = v.z; d[3] = v.w;
    }
    __syncthreads();
    // ---- transpose Xnat[m][k] -> Xt[k][mcol] (conflict-free col reads) ----
    #pragma unroll
    for (int i = 0; i < 16; ++i) {
        int idx = tid + i * THREADS;         // 0..4095
        int m4 = idx & 15;                   // m group of 4
        int k  = idx >> 4;                   // 0..255
        const float* s = Xnat + (m4 * 4) * XN_STRIDE + k;
        float4 v;
        v.x = s[0];
        v.y = s[XN_STRIDE];
        v.z = s[2 * XN_STRIDE];
        v.w = s[3 * XN_STRIDE];
        int mcol = m4 * 4 + (m4 >= 8 ? 4 : 0);
        *reinterpret_cast<float4*>(Xt + k * XT_STRIDE + mcol) = v;
    }
    // ---- relative-position bias table (no alias with Xnat) ----
    #pragma unroll
    for (int i = 0; i < 16; ++i) {
        int idx = tid + i * THREADS;
        int q = idx >> 6, k = idx & 63;
        int ri = (q >> 3) - (k >> 3) + 7;
        int rj = (q & 7)  - (k & 7)  + 7;
        Bs[q * LS_STRIDE + k] = pos_bias[ri * 15 + rj];
    }
    // first __syncthreads of the kt loop orders: transpose reads of Xnat done
    // before Ws overwrites it, and Xt writes before inner-loop reads.

    const int tm8   = (tid & 7) * 8;                     // GEMM0 m base (8 rows)
    const int tmcol = tm8 + (tm8 >= 32 ? 4 : 0);         // shifted column
    const int tn6   = (tid >> 3) * 6;                    // GEMM0 n base (0..186)

    for (int hp = 0; hp < Hc / 2; ++hp) {  // head pairs
        const int h0 = hp * 2;
        // ============ GEMM0: [Q|K|V] for heads h0,h0+1 : 64 x 192 ============
        ull acc2[8][3];
        #pragma unroll
        for (int i = 0; i < 8; ++i)
            #pragma unroll
            for (int j = 0; j < 3; ++j) acc2[i][j] = 0ull;

        for (int kt = 0; kt < 4; ++kt) {
            const int k0 = kt * 64;
            __syncthreads();
            // stage Ws[kk][row]: rows 0..95 head h0 (Wq|Wk|Wv x32), 96..191 head h0+1
            #pragma unroll
            for (int i = 0; i < 12; ++i) {
                int f4 = tid + i * THREADS;   // 0..3071
                int row = f4 >> 4;            // 0..191
                int k4  = f4 & 15;
                int hh  = row >= 96;
                int rr  = row - 96 * hh;
                int h   = h0 + hh;
                const float* src;
                if (rr < 32)      src = wq + (h * 32 + rr) * Dc;
                else if (rr < 64) src = wk + (h * 32 + rr - 32) * Dc;
                else              src = wv + (h * 32 + rr - 64) * Dc;
                float4 v = *reinterpret_cast<const float4*>(src + k0 + k4 * 4);
                float* d = Ws + (k4 * 4) * WS_STRIDE + row;
                d[0] = v.x; d[WS_STRIDE] = v.y; d[2 * WS_STRIDE] = v.z; d[3 * WS_STRIDE] = v.w;
            }
            __syncthreads();

            const float* xr = Xt + k0 * XT_STRIDE + tmcol;
            const float* wr = Ws + tn6;
            #pragma unroll 4
            for (int kk = 0; kk < 64; ++kk) {
                float4 a0 = *reinterpret_cast<const float4*>(xr);
                float4 a1 = *reinterpret_cast<const float4*>(xr + 4);
                ull b0 = *reinterpret_cast<const ull*>(wr);
                ull b1 = *reinterpret_cast<const ull*>(wr + 2);
                ull b2 = *reinterpret_cast<const ull*>(wr + 4);
                ull pa[8];
                pa[0] = pack2(a0.x); pa[1] = pack2(a0.y);
                pa[2] = pack2(a0.z); pa[3] = pack2(a0.w);
                pa[4] = pack2(a1.x); pa[5] = pack2(a1.y);
                pa[6] = pack2(a1.z); pa[7] = pack2(a1.w);
                #pragma unroll
                for (int i = 0; i < 8; ++i) {
                    ffma2(acc2[i][0], pa[i], b0);
                    ffma2(acc2[i][1], pa[i], b1);
                    ffma2(acc2[i][2], pa[i], b2);
                }
                xr += XT_STRIDE;
                wr += WS_STRIDE;
            }
        }

        // ---- scatter: Qt2 (pre-scaled, [d][m]), Kt2 ([d][m]), Vh2 ([m][d]) ----
        {
            float av[8][6];
            #pragma unroll
            for (int i = 0; i < 8; ++i)
                #pragma unroll
                for (int j = 0; j < 3; ++j) {
                    float2 t = unpack2(acc2[i][j]);
                    av[i][2 * j] = t.x; av[i][2 * j + 1] = t.y;
                }
            #pragma unroll
            for (int jj = 0; jj < 6; ++jj) {
                int col = tn6 + jj;
                int hh = col >= 96;
                int cc = col - 96 * hh;
                int h  = h0 + hh;
                if (cc < 32) {
                    float bb = bq[h * 32 + cc];
                    float* d = Qt2 + hh * 32 * QK_STRIDE + cc * QK_STRIDE + tm8;
                    #pragma unroll
                    for (int i = 0; i < 8; ++i) d[i] = (av[i][jj] + bb) * QSCALE;
                } else if (cc < 64) {
                    int c = cc - 32;
                    float bb = bk[h * 32 + c];
                    float* d = Kt2 + hh * 32 * QK_STRIDE + c * QK_STRIDE + tm8;
                    #pragma unroll
                    for (int i = 0; i < 8; ++i) d[i] = av[i][jj] + bb;
                } else {
                    int c = cc - 64;
                    float bb = bvp[h * 32 + c];
                    float* d = Vh2 + hh * 2048 + tm8 * 32 + c;
                    #pragma unroll
                    for (int i = 0; i < 8; ++i) d[i * 32] = av[i][jj] + bb;
                }
            }
        }
        __syncthreads();

        // =================== attention for the two heads =====================
        for (int hh = 0; hh < 2; ++hh) {
            const int h = h0 + hh;
            const float* Qh = Qt2 + hh * 32 * QK_STRIDE;
            const float* Kh = Kt2 + hh * 32 * QK_STRIDE;
            const float* Vp = Vh2 + hh * 2048;

            // ---- GEMM1: logits = Qs @ K^T (+bias, mask) ----
            {
                const int q0 = (tid & 15) * 4;
                const int k0 = (tid >> 4) * 4;
                ull s2[4][2];
                #pragma unroll
                for (int i = 0; i < 4; ++i) { s2[i][0] = 0ull; s2[i][1] = 0ull; }
                #pragma unroll 8
                for (int d = 0; d < 32; ++d) {
                    float4 a = *reinterpret_cast<const float4*>(Qh + d * QK_STRIDE + q0);
                    const ull* bp = reinterpret_cast<const ull*>(Kh + d * QK_STRIDE + k0);
                    ull b0 = bp[0], b1 = bp[1];
                    ull pa0 = pack2(a.x), pa1 = pack2(a.y), pa2 = pack2(a.z), pa3 = pack2(a.w);
                    ffma2(s2[0][0], pa0, b0); ffma2(s2[0][1], pa0, b1);
                    ffma2(s2[1][0], pa1, b0); ffma2(s2[1][1], pa1, b1);
                    ffma2(s2[2][0], pa2, b0); ffma2(s2[2][1], pa2, b1);
                    ffma2(s2[3][0], pa3, b0); ffma2(s2[3][1], pa3, b1);
                }
                const unsigned char* mp = mask + ((size_t)(nw * Hc + h) << 12);
                #pragma unroll
                for (int i = 0; i < 4; ++i) {
                    int q = q0 + i;
                    float4 bias4 = *reinterpret_cast<const float4*>(Bs + q * LS_STRIDE + k0);
                    unsigned int mw = *reinterpret_cast<const unsigned int*>(mp + q * 64 + k0);
                    float2 p0 = unpack2(s2[i][0]);
                    float2 p1 = unpack2(s2[i][1]);
                    float v0 = p0.x + bias4.x;
                    float v1 = p0.y + bias4.y;
                    float v2 = p1.x + bias4.z;
                    float v3 = p1.y + bias4.w;
                    if (mw) {
                        if (mw & 0x000000ffu) v0 = NEG_INF;
                        if (mw & 0x0000ff00u) v1 = NEG_INF;
                        if (mw & 0x00ff0000u) v2 = NEG_INF;
                        if (mw & 0xff000000u) v3 = NEG_INF;
                    }
                    *reinterpret_cast<float4*>(Ls + q * LS_STRIDE + k0) =
                        make_float4(v0, v1, v2, v3);
                }
            }
            __syncthreads();

            // ---- log_softmax over k, store transposed At[k][q] ----
            {
                const int q = tid >> 2;
                const int r = tid & 3;
                const float* lp = Ls + q * LS_STRIDE + r * 16;
                float x[16];
                #pragma unroll
                for (int i = 0; i < 4; ++i) {
                    float4 v = *reinterpret_cast<const float4*>(lp + i * 4);
                    x[4 * i + 0] = v.x; x[4 * i + 1] = v.y;
                    x[4 * i + 2] = v.z; x[4 * i + 3] = v.w;
                }
                float mx = x[0];
                #pragma unroll
                for (int i = 1; i < 16; ++i) mx = fmaxf(mx, x[i]);
                mx = fmaxf(mx, __shfl_xor_sync(0xffffffffu, mx, 1));
                mx = fmaxf(mx, __shfl_xor_sync(0xffffffffu, mx, 2));
                float ssum = 0.f;
                #pragma unroll
                for (int i = 0; i < 16; ++i) ssum += __expf(x[i] - mx);
                ssum += __shfl_xor_sync(0xffffffffu, ssum, 1);
                ssum += __shfl_xor_sync(0xffffffffu, ssum, 2);
                float lse = mx + __logf(ssum);
                #pragma unroll
                for (int i = 0; i < 16; ++i)
                    At[(r * 16 + i) * LS_STRIDE + q] = x[i] - lse;
            }
            __syncthreads();

            // ---- GEMM2: out_h = attn @ V (64 x 32) ----
            {
                const int q0 = (tid & 15) * 4;
                const int d0 = (tid >> 4) * 2;
                ull o2[4];
                #pragma unroll
                for (int i = 0; i < 4; ++i) o2[i] = 0ull;
                const float* vp = Vp + d0;
                #pragma unroll 8
                for (int k = 0; k < 64; ++k) {
                    float4 a = *reinterpret_cast<const float4*>(At + k * LS_STRIDE + q0);
                    ull b = *reinterpret_cast<const ull*>(vp + k * 32);
                    ffma2(o2[0], pack2(a.x), b);
                    ffma2(o2[1], pack2(a.y), b);
                    ffma2(o2[2], pack2(a.z), b);
                    ffma2(o2[3], pack2(a.w), b);
                }
                #pragma unroll
                for (int i = 0; i < 4; ++i) {
                    float2 t = unpack2(o2[i]);
                    *reinterpret_cast<float2*>(Og + (q0 + i) * Dc + h * 32 + d0) = t;
                }
            }
            // next hh: GEMM1 writes Ls (disjoint from At/Vh2 reads); the sync
            // after that GEMM1 orders GEMM2's At reads before softmax rewrites.
        }
        // next hp: first sync of the kt loop protects Ws/Qt2/Kt2/Vh2 reuse.
    }
}

extern "C" void kernel_launch(void* const* d_in, const int* in_sizes, int n_in,
                              void* d_out, int out_size) {
    (void)in_sizes; (void)n_in; (void)out_size;
    const float* patches = (const float*)d_in[0];
    const float* wq = (const float*)d_in[1];
    const float* bq = (const float*)d_in[2];
    const float* wk = (const float*)d_in[3];
    const float* bk = (const float*)d_in[4];
    const float* wv = (const float*)d_in[5];
    const float* bv = (const float*)d_in[6];
    const float* pos = (const float*)d_in[7];
    const unsigned char* mask = (const unsigned char*)d_in[8];
    float* out = (float*)d_out;

    const size_t smem_bytes = (size_t)SMEM_FLOATS * sizeof(float);  // 222720 B
    cudaFuncSetAttribute(swin_attn_kernel,
                         cudaFuncAttributeMaxDynamicSharedMemorySize,
                         (int)smem_bytes);
    swin_attn_kernel<<<16 * 256, THREADS, smem_bytes>>>(
        patches, wq, bq, wk, bk, wv, bv, pos, mask, out);
}

// round 6
// speedup vs baseline: 1.1914x; 1.1478x over previous
#include <cuda_runtime.h>
#include <cstdint>
#include <cstddef>

// ---------------------------------------------------------------------------
// SwinSelfAttention fused kernel v3
//   fp32, packed f32x2 FFMA, 512 threads/block (16 warps), 4 heads per pass.
//   B=16, NW=256, S=64, D=256, H=8, HD=32. One block per window.
// ---------------------------------------------------------------------------

namespace {
constexpr int Sc = 64;
constexpr int Dc = 256;
constexpr int Hc = 8;
constexpr int NWc = 256;
constexpr int THREADS = 512;
constexpr float QSCALE = 0.17677669529663688f;  // 1/sqrt(32)

constexpr int XT_STRIDE = 68;   // Xt[k=256][68]: cols 0..31 = m 0..31, 36..67 = m 32..63
constexpr int XN_STRIDE = 257;  // staging Xnat[m=64][257]
constexpr int WS_STRIDE = 386;  // Ws4[k=64][386] (384 rows used: 4 heads x (q|k|v)x32)
constexpr int QK_STRIDE = 68;   // per-head Qt/Kt [32][68]
constexpr int LS_STRIDE = 68;

constexpr int OFF_XT = 0;                            // 17408 floats
constexpr int OFF_U  = OFF_XT + 256 * XT_STRIDE;     // union base
constexpr int OFF_WS = OFF_U;                        // 64*386 = 24704 (transient)
constexpr int OFF_QT = OFF_U;                        // 4*32*68 = 8704 (aliases Ws4)
constexpr int OFF_KT = OFF_QT + 4 * 32 * QK_STRIDE;  // +8704
constexpr int OFF_VH = OFF_KT + 4 * 32 * QK_STRIDE;  // +8704, size 4*64*32 = 8192
constexpr int UNION_FLOATS = 3 * 8704 + 0;           // 26112 >= 24704 (Ws4) and >= 16448 (Xnat)
constexpr int OFF_LS = OFF_U + UNION_FLOATS;
constexpr int OFF_AT = OFF_LS + 64 * LS_STRIDE;
constexpr int OFF_BS = OFF_AT + 64 * LS_STRIDE;
constexpr int SMEM_FLOATS = OFF_BS + 64 * LS_STRIDE;  // 56576 floats = 226304 B
static_assert(UNION_FLOATS >= 64 * WS_STRIDE, "Ws4 must fit union");
static_assert(UNION_FLOATS >= 64 * XN_STRIDE, "Xnat must fit union");
static_assert(SMEM_FLOATS * 4 <= 232448, "must fit 227KB smem");

using ull = unsigned long long;
}  // namespace

__device__ __forceinline__ void ffma2(ull& d, ull a, ull b) {
    asm("fma.rn.f32x2 %0, %1, %2, %0;" : "+l"(d) : "l"(a), "l"(b));
}
__device__ __forceinline__ ull pack2(float x) {
    ull r; unsigned u = __float_as_uint(x);
    asm("mov.b64 %0, {%1, %1};" : "=l"(r) : "r"(u));
    return r;
}
__device__ __forceinline__ float2 unpack2(ull v) {
    unsigned lo, hi;
    asm("mov.b64 {%0, %1}, %2;" : "=r"(lo), "=r"(hi) : "l"(v));
    return make_float2(__uint_as_float(lo), __uint_as_float(hi));
}

__global__ void __launch_bounds__(THREADS, 1)
swin_attn_kernel(const float* __restrict__ patches,
                 const float* __restrict__ wq, const float* __restrict__ bq,
                 const float* __restrict__ wk, const float* __restrict__ bk,
                 const float* __restrict__ wv, const float* __restrict__ bvp,
                 const float* __restrict__ pos_bias,
                 const unsigned char* __restrict__ mask,
                 float* __restrict__ out) {
    extern __shared__ float sm[];
    float* Xt   = sm + OFF_XT;
    float* Xnat = sm + OFF_U;     // transient
    float* Ws   = sm + OFF_WS;    // transient per kt-stage
    float* Qt4  = sm + OFF_QT;    // valid after scatter, until next pass's Ws stage
    float* Kt4  = sm + OFF_KT;
    float* Vh4  = sm + OFF_VH;
    float* Ls   = sm + OFF_LS;
    float* At   = sm + OFF_AT;
    float* Bs   = sm + OFF_BS;

    const int tid = threadIdx.x;
    const int bw  = blockIdx.x;
    const int nw  = bw & (NWc - 1);
    const float* Xg = patches + (size_t)bw * (Sc * Dc);
    float* Og = out + (size_t)bw * (Sc * Dc);
    const float NEG_INF = __int_as_float(0xff800000);

    // ---- stage X (64x256) into Xnat[m][k] ----
    #pragma unroll
    for (int i = 0; i < 8; ++i) {
        int f4 = tid + i * THREADS;          // 0..4095
        int m = f4 >> 6, k4 = f4 & 63;
        float4 v = *reinterpret_cast<const float4*>(Xg + m * Dc + k4 * 4);
        float* d = Xnat + m * XN_STRIDE + k4 * 4;
        d[0] = v.x; d[1] = v.y; d[2] = v.z; d[3] = v.w;
    }
    __syncthreads();
    // ---- transpose -> Xt[k][mcol] ----
    #pragma unroll
    for (int i = 0; i < 8; ++i) {
        int idx = tid + i * THREADS;         // 0..4095
        int m4 = idx & 15;
        int k  = idx >> 4;                   // 0..255
        const float* s = Xnat + (m4 * 4) * XN_STRIDE + k;
        float4 v;
        v.x = s[0];
        v.y = s[XN_STRIDE];
        v.z = s[2 * XN_STRIDE];
        v.w = s[3 * XN_STRIDE];
        int mcol = m4 * 4 + (m4 >= 8 ? 4 : 0);
        *reinterpret_cast<float4*>(Xt + k * XT_STRIDE + mcol) = v;
    }
    // ---- relative-position bias table (outside union) ----
    #pragma unroll
    for (int i = 0; i < 8; ++i) {
        int idx = tid + i * THREADS;
        int q = idx >> 6, k = idx & 63;
        int ri = (q >> 3) - (k >> 3) + 7;
        int rj = (q & 7)  - (k & 7)  + 7;
        Bs[q * LS_STRIDE + k] = pos_bias[ri * 15 + rj];
    }
    // first sync at kt-loop top orders Xnat reads before Ws writes, Xt writes
    // before inner-loop reads.

    const int tm8   = (tid & 7) * 8;               // m base (8 rows)
    const int tmcol = tm8 + (tm8 >= 32 ? 4 : 0);   // shifted Xt column
    const int tn6   = (tid >> 3) * 6;              // col base (0..378)

    for (int pass = 0; pass < 2; ++pass) {  // 4 heads per pass
        const int hbase = pass * 4;
        // ============ GEMM0: [Q|K|V] for 4 heads : 64 x 384 =================
        ull acc2[4][6];  // m-pairs x 6 cols
        #pragma unroll
        for (int i = 0; i < 4; ++i)
            #pragma unroll
            for (int j = 0; j < 6; ++j) acc2[i][j] = 0ull;

        for (int kt = 0; kt < 4; ++kt) {
            const int k0 = kt * 64;
            __syncthreads();  // prior union consumers done
            // stage Ws[k][row]: row = hl*96 + (q|k|v)*32 + c
            #pragma unroll
            for (int i = 0; i < 12; ++i) {
                int f4 = tid + i * THREADS;   // 0..6143
                int row = f4 >> 4;            // 0..383
                int k4  = f4 & 15;
                int hl  = row / 96;
                int rr  = row - hl * 96;
                int h   = hbase + hl;
                const float* src;
                if (rr < 32)      src = wq + (h * 32 + rr) * Dc;
                else if (rr < 64) src = wk + (h * 32 + rr - 32) * Dc;
                else              src = wv + (h * 32 + rr - 64) * Dc;
                float4 v = *reinterpret_cast<const float4*>(src + k0 + k4 * 4);
                float* d = Ws + (k4 * 4) * WS_STRIDE + row;
                d[0] = v.x; d[WS_STRIDE] = v.y; d[2 * WS_STRIDE] = v.z; d[3 * WS_STRIDE] = v.w;
            }
            __syncthreads();

            const float* xr = Xt + k0 * XT_STRIDE + tmcol;
            const float* wr = Ws + tn6;
            #pragma unroll 4
            for (int kk = 0; kk < 64; ++kk) {
                ulonglong2 A0 = *reinterpret_cast<const ulonglong2*>(xr);
                ulonglong2 A1 = *reinterpret_cast<const ulonglong2*>(xr + 4);
                float2 b01 = *reinterpret_cast<const float2*>(wr);
                float2 b23 = *reinterpret_cast<const float2*>(wr + 2);
                float2 b45 = *reinterpret_cast<const float2*>(wr + 4);
                ull pa[4] = {A0.x, A0.y, A1.x, A1.y};
                ull pb[6] = {pack2(b01.x), pack2(b01.y), pack2(b23.x),
                             pack2(b23.y), pack2(b45.x), pack2(b45.y)};
                #pragma unroll
                for (int i = 0; i < 4; ++i)
                    #pragma unroll
                    for (int j = 0; j < 6; ++j)
                        ffma2(acc2[i][j], pa[i], pb[j]);
                xr += XT_STRIDE;
                wr += WS_STRIDE;
            }
        }
        __syncthreads();  // all inner-loop Ws reads done before scatter aliases it

        // ---- scatter: Qt4 (pre-scaled, [d][m]), Kt4 ([d][m]), Vh4 ([m][d]) ----
        #pragma unroll
        for (int jj = 0; jj < 6; ++jj) {
            int col = tn6 + jj;
            int hl  = col / 96;
            int cc  = col - hl * 96;
            int h   = hbase + hl;
            if (cc < 32) {
                float bb = bq[h * 32 + cc];
                float* d = Qt4 + hl * (32 * QK_STRIDE) + cc * QK_STRIDE + tm8;
                #pragma unroll
                for (int i = 0; i < 4; ++i) {
                    float2 t = unpack2(acc2[i][jj]);
                    *reinterpret_cast<float2*>(d + 2 * i) =
                        make_float2((t.x + bb) * QSCALE, (t.y + bb) * QSCALE);
                }
            } else if (cc < 64) {
                int c = cc - 32;
                float bb = bk[h * 32 + c];
                float* d = Kt4 + hl * (32 * QK_STRIDE) + c * QK_STRIDE + tm8;
                #pragma unroll
                for (int i = 0; i < 4; ++i) {
                    float2 t = unpack2(acc2[i][jj]);
                    *reinterpret_cast<float2*>(d + 2 * i) = make_float2(t.x + bb, t.y + bb);
                }
            } else {
                int c = cc - 64;
                float bb = bvp[h * 32 + c];
                float* d = Vh4 + hl * 2048 + tm8 * 32 + c;
                #pragma unroll
                for (int i = 0; i < 4; ++i) {
                    float2 t = unpack2(acc2[i][jj]);
                    d[(2 * i) * 32]     = t.x + bb;
                    d[(2 * i + 1) * 32] = t.y + bb;
                }
            }
        }
        __syncthreads();

        // =================== attention, one head at a time ===================
        for (int hh = 0; hh < 4; ++hh) {
            const int h = hbase + hh;
            const float* Qh = Qt4 + hh * (32 * QK_STRIDE);
            const float* Kh = Kt4 + hh * (32 * QK_STRIDE);
            const float* Vp = Vh4 + hh * 2048;

            // ---- GEMM1: logits = Qs @ K^T (+bias, mask) (256 threads) ----
            if (tid < 256) {
                const int q0 = (tid & 15) * 4;
                const int k0 = (tid >> 4) * 4;
                ull s2[4][2];
                #pragma unroll
                for (int i = 0; i < 4; ++i) { s2[i][0] = 0ull; s2[i][1] = 0ull; }
                #pragma unroll 8
                for (int d = 0; d < 32; ++d) {
                    float4 a = *reinterpret_cast<const float4*>(Qh + d * QK_STRIDE + q0);
                    const ull* bp = reinterpret_cast<const ull*>(Kh + d * QK_STRIDE + k0);
                    ull b0 = bp[0], b1 = bp[1];
                    ull pa0 = pack2(a.x), pa1 = pack2(a.y), pa2 = pack2(a.z), pa3 = pack2(a.w);
                    ffma2(s2[0][0], pa0, b0); ffma2(s2[0][1], pa0, b1);
                    ffma2(s2[1][0], pa1, b0); ffma2(s2[1][1], pa1, b1);
                    ffma2(s2[2][0], pa2, b0); ffma2(s2[2][1], pa2, b1);
                    ffma2(s2[3][0], pa3, b0); ffma2(s2[3][1], pa3, b1);
                }
                const unsigned char* mp = mask + ((size_t)(nw * Hc + h) << 12);
                #pragma unroll
                for (int i = 0; i < 4; ++i) {
                    int q = q0 + i;
                    float4 bias4 = *reinterpret_cast<const float4*>(Bs + q * LS_STRIDE + k0);
                    unsigned int mw = *reinterpret_cast<const unsigned int*>(mp + q * 64 + k0);
                    float2 p0 = unpack2(s2[i][0]);
                    float2 p1 = unpack2(s2[i][1]);
                    float v0 = p0.x + bias4.x;
                    float v1 = p0.y + bias4.y;
                    float v2 = p1.x + bias4.z;
                    float v3 = p1.y + bias4.w;
                    if (mw) {
                        if (mw & 0x000000ffu) v0 = NEG_INF;
                        if (mw & 0x0000ff00u) v1 = NEG_INF;
                        if (mw & 0x00ff0000u) v2 = NEG_INF;
                        if (mw & 0xff000000u) v3 = NEG_INF;
                    }
                    *reinterpret_cast<float4*>(Ls + q * LS_STRIDE + k0) =
                        make_float4(v0, v1, v2, v3);
                }
            }
            __syncthreads();

            // ---- log_softmax over k, store transposed At[k][q] (256 threads) ----
            if (tid < 256) {
                const int q = tid >> 2;
                const int r = tid & 3;
                const float* lp = Ls + q * LS_STRIDE + r * 16;
                float x[16];
                #pragma unroll
                for (int i = 0; i < 4; ++i) {
                    float4 v = *reinterpret_cast<const float4*>(lp + i * 4);
                    x[4 * i + 0] = v.x; x[4 * i + 1] = v.y;
                    x[4 * i + 2] = v.z; x[4 * i + 3] = v.w;
                }
                float mx = x[0];
                #pragma unroll
                for (int i = 1; i < 16; ++i) mx = fmaxf(mx, x[i]);
                mx = fmaxf(mx, __shfl_xor_sync(0xffffffffu, mx, 1));
                mx = fmaxf(mx, __shfl_xor_sync(0xffffffffu, mx, 2));
                float ssum = 0.f;
                #pragma unroll
                for (int i = 0; i < 16; ++i) ssum += __expf(x[i] - mx);
                ssum += __shfl_xor_sync(0xffffffffu, ssum, 1);
                ssum += __shfl_xor_sync(0xffffffffu, ssum, 2);
                float lse = mx + __logf(ssum);
                #pragma unroll
                for (int i = 0; i < 16; ++i)
                    At[(r * 16 + i) * LS_STRIDE + q] = x[i] - lse;
            }
            __syncthreads();

            // ---- GEMM2: out_h = attn @ V (64 x 32) (256 threads) ----
            if (tid < 256) {
                const int q0 = (tid & 15) * 4;
                const int d0 = (tid >> 4) * 2;
                ull o2[4];
                #pragma unroll
                for (int i = 0; i < 4; ++i) o2[i] = 0ull;
                const float* vp = Vp + d0;
                #pragma unroll 8
                for (int k = 0; k < 64; ++k) {
                    float4 a = *reinterpret_cast<const float4*>(At + k * LS_STRIDE + q0);
                    ull b = *reinterpret_cast<const ull*>(vp + k * 32);
                    ffma2(o2[0], pack2(a.x), b);
                    ffma2(o2[1], pack2(a.y), b);
                    ffma2(o2[2], pack2(a.z), b);
                    ffma2(o2[3], pack2(a.w), b);
                }
                #pragma unroll
                for (int i = 0; i < 4; ++i) {
                    float2 t = unpack2(o2[i]);
                    *reinterpret_cast<float2*>(Og + (q0 + i) * Dc + h * 32 + d0) = t;
                }
            }
            // no sync needed: next GEMM1 writes Ls only (disjoint from At/Vh4
            // reads); the sync after it orders At rewrites.
        }
        // kt-top sync of next pass protects union (Qt4/Kt4/Vh4) reuse.
    }
}

extern "C" void kernel_launch(void* const* d_in, const int* in_sizes, int n_in,
                              void* d_out, int out_size) {
    (void)in_sizes; (void)n_in; (void)out_size;
    const float* patches = (const float*)d_in[0];
    const float* wq = (const float*)d_in[1];
    const float* bq = (const float*)d_in[2];
    const float* wk = (const float*)d_in[3];
    const float* bk = (const float*)d_in[4];
    const float* wv = (const float*)d_in[5];
    const float* bv = (const float*)d_in[6];
    const float* pos = (const float*)d_in[7];
    const unsigned char* mask = (const unsigned char*)d_in[8];
    float* out = (float*)d_out;

    const size_t smem_bytes = (size_t)SMEM_FLOATS * sizeof(float);  // 226304 B
    cudaFuncSetAttribute(swin_attn_kernel,
                         cudaFuncAttributeMaxDynamicSharedMemorySize,
                         (int)smem_bytes);
    swin_attn_kernel<<<16 * 256, THREADS, smem_bytes>>>(
        patches, wq, bq, wk, bk, wv, bv, pos, mask, out);
}